// round 13
// baseline (speedup 1.0000x reference)
#include <cuda_runtime.h>
#include <math.h>

#define EPSF 1e-5f
#define SPT_STR 256   // feature-major row stride (ND <= 256)

typedef unsigned long long ull;

// leaky_relu(z, 0.01) == 0.505*z + 0.495*|z|
__device__ __forceinline__ float lrelu(float z) {
    return fmaf(0.495f, fabsf(z), 0.505f * z);
}

// packed helpers (sm_103a f32x2 pipe)
#define FMA2(acc, a, b) \
    asm("fma.rn.f32x2 %0, %1, %2, %0;" : "+l"(acc) : "l"(a), "l"(b))
#define AND2(d, s, m) \
    asm("and.b64 %0, %1, %2;" : "=l"(d) : "l"(s), "l"(m))
#define PACK2(d, x) \
    asm("mov.b64 %0, {%1, %1};" : "=l"(d) : "r"(__float_as_uint(x)))
#define PACK2U(d, x) \
    asm("mov.b64 %0, {%1, %1};" : "=l"(d) : "r"(x))
#define UNPACK2(lo, hi, s) \
    asm("mov.b64 {%0, %1}, %2;" : "=r"(lo), "=r"(hi) : "l"(s))

__global__ __launch_bounds__(256, 6) void netlocal_kernel(
    const float* __restrict__ x0g,   // [B,T,3]
    const float* __restrict__ xg,    // [B,T,ND,3]
    const int*   __restrict__ Ng,    // [B,T]
    const float* __restrict__ basisg,// [B,3,3]
    const float* __restrict__ vg,    // [B,T,ND,3]
    const float* __restrict__ Pg,    // [B]
    const float* __restrict__ W0,    // [19,127]
    const float* __restrict__ b0,    // [127]
    const float* __restrict__ W1,    // [128,128]
    const float* __restrict__ b1,    // [128]
    const float* __restrict__ W2,    // [128,128]
    const float* __restrict__ b2,    // [128]
    float*       __restrict__ outg,  // [B,T,128]
    int T, int ND)
{
    const int bt  = blockIdx.x;
    const int b   = bt / T;
    const int tid = threadIdx.x;

    __shared__ __align__(16) float spT[9 * SPT_STR];  // feature-major
    __shared__ float fblk[10];
    __shared__ float sv0[3];
    __shared__ float wsum[8][3];
    __shared__ float zcs[128];        // per-column z-constant for MLP0
    __shared__ float poolp[128 * 3];  // [col][slice], stride 3 conflict-free
    __shared__ __align__(16) float sh[128];
    __shared__ __align__(16) float sh1[128];
    __shared__ __align__(16) float pDv[8][128];  // Phase-D split-k partials

    const float* bas   = basisg + b * 9;   // uniform-address, L1-resident
    const float* vbase = vg + (size_t)bt * ND * 3;
    const float* xbase = xg + (size_t)bt * ND * 3;

    // ---- Phase A: one particle per thread (ND <= 256). Load x and v ONCE,
    //      compute x-features now (independent of v0), cache xu and v. ----
    float xux = 0.f, xuy = 0.f, xuz = 0.f;   // cached unit x
    float vpx = 0.f, vpy = 0.f, vpz = 0.f;   // cached raw v
    {
        float vx = 0.f, vy = 0.f, vz = 0.f;
        if (tid < ND) {
            const float ax = xbase[tid * 3 + 0];
            const float ay = xbase[tid * 3 + 1];
            const float az = xbase[tid * 3 + 2];
            vpx = vbase[tid * 3 + 0];
            vpy = vbase[tid * 3 + 1];
            vpz = vbase[tid * 3 + 2];
            vx = vpx; vy = vpy; vz = vpz;

            const float xn = sqrtf(ax * ax + ay * ay + az * az) + EPSF;
            const float ir = 1.0f / xn;
            xux = ax * ir; xuy = ay * ir; xuz = az * ir;

            spT[0 * SPT_STR + tid] = xn;
            spT[1 * SPT_STR + tid] = xux * bas[0] + xuy * bas[1] + xuz * bas[2];
            spT[2 * SPT_STR + tid] = xux * bas[3] + xuy * bas[4] + xuz * bas[5];
            spT[3 * SPT_STR + tid] = xux * bas[6] + xuy * bas[7] + xuz * bas[8];
        }
        // deterministic tree reduction of v
#pragma unroll
        for (int o = 16; o > 0; o >>= 1) {
            vx += __shfl_xor_sync(0xffffffffu, vx, o);
            vy += __shfl_xor_sync(0xffffffffu, vy, o);
            vz += __shfl_xor_sync(0xffffffffu, vz, o);
        }
        if ((tid & 31) == 0) {
            wsum[tid >> 5][0] = vx;
            wsum[tid >> 5][1] = vy;
            wsum[tid >> 5][2] = vz;
        }
    }
    __syncthreads();

    if (tid == 0) {
        float sx = 0.f, sy = 0.f, sz = 0.f;
#pragma unroll
        for (int w = 0; w < 8; w++) { sx += wsum[w][0]; sy += wsum[w][1]; sz += wsum[w][2]; }
        const float invN = 1.0f / (float)ND;
        const float v0x = sx * invN, v0y = sy * invN, v0z = sz * invN;
        sv0[0] = v0x; sv0[1] = v0y; sv0[2] = v0z;

        const float x00 = x0g[bt * 3 + 0], x01 = x0g[bt * 3 + 1], x02 = x0g[bt * 3 + 2];
        const float x0n = sqrtf(x00 * x00 + x01 * x01 + x02 * x02) + EPSF;
        const float ix  = 1.0f / x0n;
        const float x0ux = x00 * ix, x0uy = x01 * ix, x0uz = x02 * ix;

        const float v0n = sqrtf(v0x * v0x + v0y * v0y + v0z * v0z) + EPSF;
        const float iv  = 1.0f / v0n;
        const float v0ux = v0x * iv, v0uy = v0y * iv, v0uz = v0z * iv;

        fblk[0] = log1pf((float)Ng[bt]);                             // f4
        fblk[1] = x0n;                                               // f5
        fblk[2] = x0ux * bas[0] + x0uy * bas[1] + x0uz * bas[2];     // f6
        fblk[3] = x0ux * bas[3] + x0uy * bas[4] + x0uz * bas[5];     // f7
        fblk[4] = x0ux * bas[6] + x0uy * bas[7] + x0uz * bas[8];     // f8
        fblk[5] = v0n;                                               // f9
        fblk[6] = v0ux * bas[0] + v0uy * bas[1] + v0uz * bas[2];     // f10
        fblk[7] = v0ux * bas[3] + v0uy * bas[4] + v0uz * bas[5];     // f11
        fblk[8] = v0ux * bas[6] + v0uy * bas[7] + v0uz * bas[8];     // f12
        fblk[9] = x0ux * v0ux + x0uy * v0uy + x0uz * v0uz;           // f13
    }
    __syncthreads();

    // ---- Phase B: v-features from cached registers (no global reloads);
    //      zcs[j] once per column (tid<128) ----
    if (tid < ND) {
        const float wx = vpx - sv0[0];
        const float wy = vpy - sv0[1];
        const float wz = vpz - sv0[2];
        const float vn = sqrtf(wx * wx + wy * wy + wz * wz) + EPSF;
        const float ivn = 1.0f / vn;
        const float vux = wx * ivn, vuy = wy * ivn, vuz = wz * ivn;

        spT[4 * SPT_STR + tid] = vn;
        spT[5 * SPT_STR + tid] = vux * bas[0] + vuy * bas[1] + vuz * bas[2];
        spT[6 * SPT_STR + tid] = vux * bas[3] + vuy * bas[4] + vuz * bas[5];
        spT[7 * SPT_STR + tid] = vux * bas[6] + vuy * bas[7] + vuz * bas[8];
        spT[8 * SPT_STR + tid] = xux * vux + xuy * vuy + xuz * vuz;
    }
    if (tid < 128) {
        float zv = 0.f;
        if (tid < 127) {
            zv = b0[tid];
#pragma unroll
            for (int i = 0; i < 10; i++)
                zv = fmaf(fblk[i], W0[(4 + i) * 127 + tid], zv);
        }
        zcs[tid] = zv;
    }
    __syncthreads();

    // ---- Phase C: MLP0 + mean pool, packed f32x2.
    //      1 column per thread (col = tid&127), slice = tid>>7 (128 particles). ----
    {
        const int col = tid & 127;
        const int sl  = tid >> 7;

        ull w2[9];
        ull zc2;
        {
            float wr[9];
            if (col < 127) {
                // per-particle feature rows of W0: {0,1,2,3,14,15,16,17,18}
                wr[0] = W0[0 * 127 + col];
                wr[1] = W0[1 * 127 + col];
                wr[2] = W0[2 * 127 + col];
                wr[3] = W0[3 * 127 + col];
                wr[4] = W0[14 * 127 + col];
                wr[5] = W0[15 * 127 + col];
                wr[6] = W0[16 * 127 + col];
                wr[7] = W0[17 * 127 + col];
                wr[8] = W0[18 * 127 + col];
            } else {
#pragma unroll
                for (int i = 0; i < 9; i++) wr[i] = 0.f;
            }
#pragma unroll
            for (int i = 0; i < 9; i++) PACK2(w2[i], wr[i]);
            PACK2(zc2, zcs[col]);
        }

        ull c505, c495, mabs;
        PACK2(c505, 0.505f);
        PACK2(c495, 0.495f);
        PACK2U(mabs, 0x7FFFFFFFu);

        const int nspl = ND >> 1;       // particles per slice (128)
        const int n0b  = sl * nspl;
        ull acc0 = 0ull, acc1 = 0ull;

        for (int i = 0; i < nspl; i += 4) {
            const int n0 = n0b + i;
            ull z0 = zc2, z1 = zc2;
#pragma unroll
            for (int k = 0; k < 9; k++) {
                // broadcast LDS.128: features of particles n0..n0+3
                const ulonglong2 qv =
                    *(const ulonglong2*)(spT + k * SPT_STR + n0);
                FMA2(z0, w2[k], qv.x);
                FMA2(z1, w2[k], qv.y);
            }
            ull a;
            AND2(a, z0, mabs); FMA2(acc0, c505, z0); FMA2(acc0, c495, a);
            AND2(a, z1, mabs); FMA2(acc1, c505, z1); FMA2(acc1, c495, a);
        }

        unsigned int l0, h0, l1, h1;
        UNPACK2(l0, h0, acc0);
        UNPACK2(l1, h1, acc1);
        const float tot = (__uint_as_float(l0) + __uint_as_float(h0)) +
                          (__uint_as_float(l1) + __uint_as_float(h1));
        poolp[col * 3 + sl] = tot;
    }
    __syncthreads();

    if (tid < 128) {
        const float sm = poolp[tid * 3 + 0] + poolp[tid * 3 + 1];
        const float pm = sm * (1.0f / (float)ND);
        sh[tid] = (tid < 127) ? pm : fblk[0];   // append log1p(N) at index 127
    }
    __syncthreads();

    // ---- Phase D: vectorized matvecs. thread -> 4 cols, 8-way split-k ----
    const int c4 = (tid & 31) * 4;
    const int s8 = tid >> 5;
    {
        ull alo = 0ull, ahi = 0ull;
        const int k0 = s8 * 16;
#pragma unroll 4
        for (int k = k0; k < k0 + 16; k++) {
            const ulonglong2 wq = *(const ulonglong2*)(W1 + k * 128 + c4);
            ull h2; PACK2(h2, sh[k]);
            FMA2(alo, wq.x, h2);
            FMA2(ahi, wq.y, h2);
        }
        *(ulonglong2*)&pDv[s8][c4] = make_ulonglong2(alo, ahi);
    }
    __syncthreads();
    if (tid < 128) {
        float a1 = b1[tid];
#pragma unroll
        for (int s = 0; s < 8; s++) a1 += pDv[s][tid];
        sh1[tid] = lrelu(a1);
    }
    __syncthreads();
    {
        ull alo = 0ull, ahi = 0ull;
        const int k0 = s8 * 16;
#pragma unroll 4
        for (int k = k0; k < k0 + 16; k++) {
            const ulonglong2 wq = *(const ulonglong2*)(W2 + k * 128 + c4);
            ull h2; PACK2(h2, sh1[k]);
            FMA2(alo, wq.x, h2);
            FMA2(ahi, wq.y, h2);
        }
        *(ulonglong2*)&pDv[s8][c4] = make_ulonglong2(alo, ahi);
    }
    __syncthreads();
    if (tid < 128) {
        float a2 = b2[tid];
#pragma unroll
        for (int s = 0; s < 8; s++) a2 += pDv[s][tid];
        outg[(size_t)bt * 128 + tid] = a2 * (1.0f / Pg[b]);
    }
}

extern "C" void kernel_launch(void* const* d_in, const int* in_sizes, int n_in,
                              void* d_out, int out_size) {
    const float* x0g    = (const float*)d_in[0];
    const float* xg     = (const float*)d_in[1];
    const int*   Ng     = (const int*)  d_in[2];
    const float* basisg = (const float*)d_in[3];
    const float* vg     = (const float*)d_in[4];
    const float* Pg     = (const float*)d_in[5];
    const float* W0     = (const float*)d_in[6];
    const float* b0     = (const float*)d_in[7];
    const float* W1     = (const float*)d_in[8];
    const float* b1     = (const float*)d_in[9];
    const float* W2     = (const float*)d_in[10];
    const float* b2     = (const float*)d_in[11];
    float* outg = (float*)d_out;

    const int B  = in_sizes[5];                       // P200c: [B]
    const int BT = in_sizes[2];                       // N: [B,T]
    const int T  = BT / B;
    const int ND = in_sizes[1] / (BT * 3);            // x: [B,T,ND,3]

    netlocal_kernel<<<BT, 256>>>(x0g, xg, Ng, basisg, vg, Pg,
                                 W0, b0, W1, b1, W2, b2, outg, T, ND);
}

// round 14
// speedup vs baseline: 1.3677x; 1.3677x over previous
#include <cuda_runtime.h>
#include <math.h>

#define EPSF 1e-5f

typedef unsigned long long ull;

// leaky_relu(z, 0.01) == 0.505*z + 0.495*|z|
__device__ __forceinline__ float lrelu(float z) {
    return fmaf(0.495f, fabsf(z), 0.505f * z);
}

// packed helpers (sm_103a f32x2 pipe)
#define FMA2(acc, a, b) \
    asm("fma.rn.f32x2 %0, %1, %2, %0;" : "+l"(acc) : "l"(a), "l"(b))
#define AND2(d, s, m) \
    asm("and.b64 %0, %1, %2;" : "=l"(d) : "l"(s), "l"(m))
#define PACK2(d, x) \
    asm("mov.b64 %0, {%1, %1};" : "=l"(d) : "r"(__float_as_uint(x)))
#define PACK2U(d, x) \
    asm("mov.b64 %0, {%1, %1};" : "=l"(d) : "r"(x))
#define UNPACK2(lo, hi, s) \
    asm("mov.b64 {%0, %1}, %2;" : "=r"(lo), "=r"(hi) : "l"(s))

__global__ __launch_bounds__(256, 4) void netlocal_kernel(
    const float* __restrict__ x0g,   // [B,T,3]
    const float* __restrict__ xg,    // [B,T,ND,3]
    const int*   __restrict__ Ng,    // [B,T]
    const float* __restrict__ basisg,// [B,3,3]
    const float* __restrict__ vg,    // [B,T,ND,3]
    const float* __restrict__ Pg,    // [B]
    const float* __restrict__ W0,    // [19,127]
    const float* __restrict__ b0,    // [127]
    const float* __restrict__ W1,    // [128,128]
    const float* __restrict__ b1,    // [128]
    const float* __restrict__ W2,    // [128,128]
    const float* __restrict__ b2,    // [128]
    float*       __restrict__ outg,  // [B,T,128]
    int T, int ND, int BT)
{
    const int bt0 = blockIdx.x * 2;
    const int tid = threadIdx.x;

    // feature-major, 2 halos: spT[k][q*256 + n]
    __shared__ __align__(16) float spT[9 * 512];
    __shared__ float fblk[2][10];
    __shared__ float sv0[2][3];
    __shared__ float wsum[2][8][3];
    __shared__ float zcs[2 * 128];       // [q*128 + col]
    __shared__ float poolp[2][128 * 5];  // [q][col*5 + slice]
    __shared__ float shq[2 * 128];       // pooled h per halo
    __shared__ float sh1q[2 * 128];
    __shared__ __align__(16) float pDvq[8][256];  // [split][q*128 + col]

    // ---- Phase A: both halos. 1 particle/thread. x-features + v-reduction. ----
    float xu[2][3];   // cached unit x per halo
    float vp[2][3];   // cached raw v per halo
#pragma unroll
    for (int q = 0; q < 2; q++) {
        const int bt = bt0 + q;
        float vx = 0.f, vy = 0.f, vz = 0.f;
#pragma unroll
        for (int d = 0; d < 3; d++) { xu[q][d] = 0.f; vp[q][d] = 0.f; }
        if (bt < BT && tid < ND) {
            const float* xb = xg + (size_t)bt * ND * 3 + tid * 3;
            const float* vb = vg + (size_t)bt * ND * 3 + tid * 3;
            const float ax = xb[0], ay = xb[1], az = xb[2];
            vp[q][0] = vb[0]; vp[q][1] = vb[1]; vp[q][2] = vb[2];
            vx = vp[q][0]; vy = vp[q][1]; vz = vp[q][2];

            const float xn = sqrtf(ax * ax + ay * ay + az * az) + EPSF;
            const float ir = 1.0f / xn;
            xu[q][0] = ax * ir; xu[q][1] = ay * ir; xu[q][2] = az * ir;

            const float* bas = basisg + (bt / T) * 9;
            spT[0 * 512 + q * 256 + tid] = xn;
            spT[1 * 512 + q * 256 + tid] =
                xu[q][0] * bas[0] + xu[q][1] * bas[1] + xu[q][2] * bas[2];
            spT[2 * 512 + q * 256 + tid] =
                xu[q][0] * bas[3] + xu[q][1] * bas[4] + xu[q][2] * bas[5];
            spT[3 * 512 + q * 256 + tid] =
                xu[q][0] * bas[6] + xu[q][1] * bas[7] + xu[q][2] * bas[8];
        }
        // deterministic tree reduction of v (all threads participate)
#pragma unroll
        for (int o = 16; o > 0; o >>= 1) {
            vx += __shfl_xor_sync(0xffffffffu, vx, o);
            vy += __shfl_xor_sync(0xffffffffu, vy, o);
            vz += __shfl_xor_sync(0xffffffffu, vz, o);
        }
        if ((tid & 31) == 0) {
            wsum[q][tid >> 5][0] = vx;
            wsum[q][tid >> 5][1] = vy;
            wsum[q][tid >> 5][2] = vz;
        }
    }
    __syncthreads();

    // ---- serial head: thread 0 -> halo 0, thread 1 -> halo 1 (parallel) ----
    if (tid < 2) {
        const int q  = tid;
        const int bt = bt0 + q;
        if (bt < BT) {
            const float* bas = basisg + (bt / T) * 9;
            float sx = 0.f, sy = 0.f, sz = 0.f;
#pragma unroll
            for (int w = 0; w < 8; w++) {
                sx += wsum[q][w][0]; sy += wsum[q][w][1]; sz += wsum[q][w][2];
            }
            const float invN = 1.0f / (float)ND;
            const float v0x = sx * invN, v0y = sy * invN, v0z = sz * invN;
            sv0[q][0] = v0x; sv0[q][1] = v0y; sv0[q][2] = v0z;

            const float x00 = x0g[bt * 3 + 0], x01 = x0g[bt * 3 + 1], x02 = x0g[bt * 3 + 2];
            const float x0n = sqrtf(x00 * x00 + x01 * x01 + x02 * x02) + EPSF;
            const float ix  = 1.0f / x0n;
            const float x0ux = x00 * ix, x0uy = x01 * ix, x0uz = x02 * ix;

            const float v0n = sqrtf(v0x * v0x + v0y * v0y + v0z * v0z) + EPSF;
            const float iv  = 1.0f / v0n;
            const float v0ux = v0x * iv, v0uy = v0y * iv, v0uz = v0z * iv;

            fblk[q][0] = log1pf((float)Ng[bt]);                           // f4
            fblk[q][1] = x0n;                                             // f5
            fblk[q][2] = x0ux * bas[0] + x0uy * bas[1] + x0uz * bas[2];   // f6
            fblk[q][3] = x0ux * bas[3] + x0uy * bas[4] + x0uz * bas[5];   // f7
            fblk[q][4] = x0ux * bas[6] + x0uy * bas[7] + x0uz * bas[8];   // f8
            fblk[q][5] = v0n;                                             // f9
            fblk[q][6] = v0ux * bas[0] + v0uy * bas[1] + v0uz * bas[2];   // f10
            fblk[q][7] = v0ux * bas[3] + v0uy * bas[4] + v0uz * bas[5];   // f11
            fblk[q][8] = v0ux * bas[6] + v0uy * bas[7] + v0uz * bas[8];   // f12
            fblk[q][9] = x0ux * v0ux + x0uy * v0uy + x0uz * v0uz;         // f13
        }
    }
    __syncthreads();

    // ---- Phase B: v-features for both halos (from cached regs) + zcs ----
#pragma unroll
    for (int q = 0; q < 2; q++) {
        const int bt = bt0 + q;
        if (bt < BT && tid < ND) {
            const float* bas = basisg + (bt / T) * 9;
            const float wx = vp[q][0] - sv0[q][0];
            const float wy = vp[q][1] - sv0[q][1];
            const float wz = vp[q][2] - sv0[q][2];
            const float vn = sqrtf(wx * wx + wy * wy + wz * wz) + EPSF;
            const float ivn = 1.0f / vn;
            const float vux = wx * ivn, vuy = wy * ivn, vuz = wz * ivn;

            spT[4 * 512 + q * 256 + tid] = vn;
            spT[5 * 512 + q * 256 + tid] = vux * bas[0] + vuy * bas[1] + vuz * bas[2];
            spT[6 * 512 + q * 256 + tid] = vux * bas[3] + vuy * bas[4] + vuz * bas[5];
            spT[7 * 512 + q * 256 + tid] = vux * bas[6] + vuy * bas[7] + vuz * bas[8];
            spT[8 * 512 + q * 256 + tid] =
                xu[q][0] * vux + xu[q][1] * vuy + xu[q][2] * vuz;
        }
    }
    {
        // zcs[tid] for q = tid>>7, col = tid&127
        const int q   = tid >> 7;
        const int col = tid & 127;
        float zv = 0.f;
        if (bt0 + q < BT && col < 127) {
            zv = b0[col];
#pragma unroll
            for (int i = 0; i < 10; i++)
                zv = fmaf(fblk[q][i], W0[(4 + i) * 127 + col], zv);
        }
        zcs[tid] = zv;
    }
    __syncthreads();

    // ---- Phase C: MLP0 + pool. Weights hoisted; two halo passes. ----
    {
        const int j63 = tid & 63;
        const int s4  = tid >> 6;

        ull w2[2][9];
#pragma unroll
        for (int c = 0; c < 2; c++) {
            const int col = j63 + 64 * c;
            float wr[9];
            if (col < 127) {
                // per-particle feature rows of W0: {0,1,2,3,14,15,16,17,18}
                wr[0] = W0[0 * 127 + col];
                wr[1] = W0[1 * 127 + col];
                wr[2] = W0[2 * 127 + col];
                wr[3] = W0[3 * 127 + col];
                wr[4] = W0[14 * 127 + col];
                wr[5] = W0[15 * 127 + col];
                wr[6] = W0[16 * 127 + col];
                wr[7] = W0[17 * 127 + col];
                wr[8] = W0[18 * 127 + col];
            } else {
#pragma unroll
                for (int i = 0; i < 9; i++) wr[i] = 0.f;
            }
#pragma unroll
            for (int i = 0; i < 9; i++) PACK2(w2[c][i], wr[i]);
        }

        ull c505, c495, mabs;
        PACK2(c505, 0.505f);
        PACK2(c495, 0.495f);
        PACK2U(mabs, 0x7FFFFFFFu);

        const int nspl = ND >> 2;       // particles per slice (64)
        const int n0b  = s4 * nspl;

#pragma unroll
        for (int q = 0; q < 2; q++) {
            ull zc0, zc1;
            PACK2(zc0, zcs[q * 128 + j63]);
            PACK2(zc1, zcs[q * 128 + j63 + 64]);
            ull acc0 = 0ull, acc1 = 0ull;
            const float* base = spT + q * 256;

            for (int i = 0; i < nspl; i += 4) {
                const int n0 = n0b + i;
                ull z00 = zc0, z01 = zc0, z10 = zc1, z11 = zc1;
#pragma unroll
                for (int k = 0; k < 9; k++) {
                    // broadcast LDS.128: 4 particles of feature k
                    const ulonglong2 qv =
                        *(const ulonglong2*)(base + k * 512 + n0);
                    FMA2(z00, w2[0][k], qv.x);
                    FMA2(z01, w2[0][k], qv.y);
                    FMA2(z10, w2[1][k], qv.x);
                    FMA2(z11, w2[1][k], qv.y);
                }
                ull a;
                AND2(a, z00, mabs); FMA2(acc0, c505, z00); FMA2(acc0, c495, a);
                AND2(a, z01, mabs); FMA2(acc0, c505, z01); FMA2(acc0, c495, a);
                AND2(a, z10, mabs); FMA2(acc1, c505, z10); FMA2(acc1, c495, a);
                AND2(a, z11, mabs); FMA2(acc1, c505, z11); FMA2(acc1, c495, a);
            }

            unsigned int l0, h0, l1, h1;
            UNPACK2(l0, h0, acc0);
            UNPACK2(l1, h1, acc1);
            poolp[q][j63 * 5 + s4]        = __uint_as_float(l0) + __uint_as_float(h0);
            poolp[q][(j63 + 64) * 5 + s4] = __uint_as_float(l1) + __uint_as_float(h1);
        }
    }
    __syncthreads();

    // ---- pool combine for both halos ----
    {
        const int q   = tid >> 7;
        const int col = tid & 127;
        float sm = 0.f;
#pragma unroll
        for (int w = 0; w < 4; w++) sm += poolp[q][col * 5 + w];
        const float pm = sm * (1.0f / (float)ND);
        shq[tid] = (col < 127) ? pm : fblk[q][0];   // append log1p(N)
    }
    __syncthreads();

    // ---- Phase D: vectorized matvecs, W loaded once for BOTH halos ----
    const int c4 = (tid & 31) * 4;
    const int s8 = tid >> 5;
    {
        ull alo0 = 0ull, ahi0 = 0ull, alo1 = 0ull, ahi1 = 0ull;
        const int k0 = s8 * 16;
#pragma unroll 4
        for (int k = k0; k < k0 + 16; k++) {
            const ulonglong2 wq = *(const ulonglong2*)(W1 + k * 128 + c4);
            ull h20, h21;
            PACK2(h20, shq[k]);
            PACK2(h21, shq[128 + k]);
            FMA2(alo0, wq.x, h20); FMA2(ahi0, wq.y, h20);
            FMA2(alo1, wq.x, h21); FMA2(ahi1, wq.y, h21);
        }
        *(ulonglong2*)&pDvq[s8][c4]       = make_ulonglong2(alo0, ahi0);
        *(ulonglong2*)&pDvq[s8][128 + c4] = make_ulonglong2(alo1, ahi1);
    }
    __syncthreads();
    {
        const int q   = tid >> 7;
        const int col = tid & 127;
        float a1 = b1[col];
#pragma unroll
        for (int s = 0; s < 8; s++) a1 += pDvq[s][q * 128 + col];
        sh1q[tid] = lrelu(a1);
    }
    __syncthreads();
    {
        ull alo0 = 0ull, ahi0 = 0ull, alo1 = 0ull, ahi1 = 0ull;
        const int k0 = s8 * 16;
#pragma unroll 4
        for (int k = k0; k < k0 + 16; k++) {
            const ulonglong2 wq = *(const ulonglong2*)(W2 + k * 128 + c4);
            ull h20, h21;
            PACK2(h20, sh1q[k]);
            PACK2(h21, sh1q[128 + k]);
            FMA2(alo0, wq.x, h20); FMA2(ahi0, wq.y, h20);
            FMA2(alo1, wq.x, h21); FMA2(ahi1, wq.y, h21);
        }
        *(ulonglong2*)&pDvq[s8][c4]       = make_ulonglong2(alo0, ahi0);
        *(ulonglong2*)&pDvq[s8][128 + c4] = make_ulonglong2(alo1, ahi1);
    }
    __syncthreads();
    {
        const int q   = tid >> 7;
        const int col = tid & 127;
        const int bt  = bt0 + q;
        if (bt < BT) {
            float a2 = b2[col];
#pragma unroll
            for (int s = 0; s < 8; s++) a2 += pDvq[s][q * 128 + col];
            outg[(size_t)bt * 128 + col] = a2 * (1.0f / Pg[bt / T]);
        }
    }
}

extern "C" void kernel_launch(void* const* d_in, const int* in_sizes, int n_in,
                              void* d_out, int out_size) {
    const float* x0g    = (const float*)d_in[0];
    const float* xg     = (const float*)d_in[1];
    const int*   Ng     = (const int*)  d_in[2];
    const float* basisg = (const float*)d_in[3];
    const float* vg     = (const float*)d_in[4];
    const float* Pg     = (const float*)d_in[5];
    const float* W0     = (const float*)d_in[6];
    const float* b0     = (const float*)d_in[7];
    const float* W1     = (const float*)d_in[8];
    const float* b1     = (const float*)d_in[9];
    const float* W2     = (const float*)d_in[10];
    const float* b2     = (const float*)d_in[11];
    float* outg = (float*)d_out;

    const int B  = in_sizes[5];                       // P200c: [B]
    const int BT = in_sizes[2];                       // N: [B,T]
    const int T  = BT / B;
    const int ND = in_sizes[1] / (BT * 3);            // x: [B,T,ND,3]

    const int grid = (BT + 1) / 2;
    netlocal_kernel<<<grid, 256>>>(x0g, xg, Ng, basisg, vg, Pg,
                                   W0, b0, W1, b1, W2, b2, outg, T, ND, BT);
}